// round 9
// baseline (speedup 1.0000x reference)
#include <cuda_runtime.h>
#include <cuda_fp16.h>
#include <math.h>

#define NN   50000
#define FIN  256
#define H1N  8
#define F1   256
#define NEG  0.2f
#define EMAX 900000
#define FULL 0xffffffffu

// ---------------- scratch ----------------
__device__ __align__(256) float  g_h1[NN * F1];
__device__ __align__(256) __half g_h1h[NN * F1];
__device__ __align__(256) float  g_el1[NN * H1N];
__device__ __align__(256) float  g_er1[NN * H1N];
__device__ __align__(256) float  g_x1[NN * F1];
__device__ __align__(256) float  g_h2res[NN * 128];   // [h2 (64) | residual (64)]
__device__ __align__(256) __half g_h2h[NN * 128];
__device__ __align__(256) float  g_el2[NN];
__device__ __align__(256) float  g_er2[NN];
__device__ __align__(256) float  g_Bcat[FIN * 128];
__device__ int g_deg[NN];          // zeroed at load; re-zeroed by k_agg2 each run
__device__ int g_off[NN + 1];
__device__ int g_us[EMAX];

// ---------------- CSR build ----------------
__global__ void k_hist(const int* __restrict__ dst, int E, int* __restrict__ deg) {
    int i = blockIdx.x * blockDim.x + threadIdx.x;
    if (i < E) atomicAdd(&deg[dst[i]], 1);
}

// single-block scan; also zeroes deg so k_scatter can reuse it as its cursor
__global__ void k_scan(int* __restrict__ deg, int* __restrict__ off, int n) {
    __shared__ int wsum[32];
    __shared__ int carry;
    int tid = threadIdx.x, lane = tid & 31, wid = tid >> 5;
    if (tid == 0) carry = 0;
    __syncthreads();
    for (int base = 0; base < n; base += 1024) {
        int i = base + tid;
        int v = 0;
        if (i < n) { v = deg[i]; deg[i] = 0; }
        int x = v;
        #pragma unroll
        for (int o = 1; o < 32; o <<= 1) {
            int y = __shfl_up_sync(FULL, x, o);
            if (lane >= o) x += y;
        }
        if (lane == 31) wsum[wid] = x;
        __syncthreads();
        if (wid == 0) {
            int w = wsum[lane];
            #pragma unroll
            for (int o = 1; o < 32; o <<= 1) {
                int y = __shfl_up_sync(FULL, w, o);
                if (lane >= o) w += y;
            }
            wsum[lane] = w;
        }
        __syncthreads();
        int incl = x + (wid ? wsum[wid - 1] : 0) + carry;
        if (i < n) off[i] = incl - v;
        __syncthreads();
        if (tid == 1023) carry = incl;
        __syncthreads();
    }
    if (tid == 0) off[n] = carry;
}

__global__ void k_scatter(const int* __restrict__ src, const int* __restrict__ dst,
                          int E, const int* __restrict__ off, int* __restrict__ cur,
                          int* __restrict__ us) {
    int i = blockIdx.x * blockDim.x + threadIdx.x;
    if (i < E) {
        int d = dst[i];
        int p = off[d] + atomicAdd(&cur[d], 1);
        us[p] = src[i];
    }
}

// ---------------- TF32 tensor-core GEMM (single-buffer, reg prefetch) ------------
// Also emits a half-precision copy of C for the gather kernels.
__device__ __forceinline__ unsigned f2tf(float x) {
    unsigned u;
    asm("cvt.rna.tf32.f32 %0, %1;" : "=r"(u) : "f"(x));
    return u;
}

__device__ __forceinline__ void mma_tf32(float* d, const unsigned* a, const unsigned* b) {
    asm volatile(
        "mma.sync.aligned.m16n8k8.row.col.f32.tf32.tf32.f32 "
        "{%0,%1,%2,%3}, {%4,%5,%6,%7}, {%8,%9}, {%0,%1,%2,%3};\n"
        : "+f"(d[0]), "+f"(d[1]), "+f"(d[2]), "+f"(d[3])
        : "r"(a[0]), "r"(a[1]), "r"(a[2]), "r"(a[3]), "r"(b[0]), "r"(b[1]));
}

__global__ __launch_bounds__(256)
void k_mma_gemm(const float* __restrict__ A, const float* __restrict__ B,
                float* __restrict__ C, __half* __restrict__ Ch,
                int M, int N, int K) {
    __shared__ unsigned As[128][36];
    __shared__ unsigned Bs[32][72];
    int t = threadIdx.x;
    int lane = t & 31;
    int warp = t >> 5;
    int g = lane >> 2, q = lane & 3;
    int warpM = warp & 3, warpN = warp >> 2;
    int bm = blockIdx.x * 128, bn = blockIdx.y * 64;

    float4 avs[4], bvs[2];
    float acc[2][4][4] = {};

    auto loadA = [&](int kt) {
        #pragma unroll
        for (int i = 0; i < 4; i++) {
            int idx = t + i * 256;
            int r = idx >> 3, c4 = (idx & 7) * 4;
            float4 v = make_float4(0.f, 0.f, 0.f, 0.f);
            if (bm + r < M)
                v = *(const float4*)&A[(size_t)(bm + r) * K + kt + c4];
            avs[i] = v;
        }
    };
    auto loadB = [&](int kt) {
        #pragma unroll
        for (int i = 0; i < 2; i++) {
            int idx = t + i * 256;
            int r = idx >> 4, c4 = (idx & 15) * 4;
            bvs[i] = *(const float4*)&B[(size_t)(kt + r) * N + bn + c4];
        }
    };
    auto stage = [&]() {
        #pragma unroll
        for (int i = 0; i < 4; i++) {
            int idx = t + i * 256;
            int r = idx >> 3, c4 = (idx & 7) * 4;
            As[r][c4 + 0] = f2tf(avs[i].x);
            As[r][c4 + 1] = f2tf(avs[i].y);
            As[r][c4 + 2] = f2tf(avs[i].z);
            As[r][c4 + 3] = f2tf(avs[i].w);
        }
        #pragma unroll
        for (int i = 0; i < 2; i++) {
            int idx = t + i * 256;
            int r = idx >> 4, c4 = (idx & 15) * 4;
            Bs[r][c4 + 0] = f2tf(bvs[i].x);
            Bs[r][c4 + 1] = f2tf(bvs[i].y);
            Bs[r][c4 + 2] = f2tf(bvs[i].z);
            Bs[r][c4 + 3] = f2tf(bvs[i].w);
        }
    };

    loadA(0); loadB(0);
    stage();
    __syncthreads();

    for (int kt = 0; kt < K; kt += 32) {
        bool nxt = (kt + 32) < K;
        if (nxt) { loadA(kt + 32); loadB(kt + 32); }

        #pragma unroll
        for (int ks = 0; ks < 4; ks++) {
            int k0 = ks * 8;
            unsigned af[2][4], bf[4][2];
            #pragma unroll
            for (int mt = 0; mt < 2; mt++) {
                int rb = warpM * 32 + mt * 16;
                af[mt][0] = As[rb + g][k0 + q];
                af[mt][1] = As[rb + g + 8][k0 + q];
                af[mt][2] = As[rb + g][k0 + q + 4];
                af[mt][3] = As[rb + g + 8][k0 + q + 4];
            }
            #pragma unroll
            for (int nt = 0; nt < 4; nt++) {
                int cb = warpN * 32 + nt * 8;
                bf[nt][0] = Bs[k0 + q][cb + g];
                bf[nt][1] = Bs[k0 + q + 4][cb + g];
            }
            #pragma unroll
            for (int mt = 0; mt < 2; mt++)
                #pragma unroll
                for (int nt = 0; nt < 4; nt++)
                    mma_tf32(acc[mt][nt], af[mt], bf[nt]);
        }
        if (nxt) {
            __syncthreads();
            stage();
            __syncthreads();
        }
    }

    #pragma unroll
    for (int mt = 0; mt < 2; mt++) {
        int r0 = bm + warpM * 32 + mt * 16 + g;
        #pragma unroll
        for (int nt = 0; nt < 4; nt++) {
            int c = bn + warpN * 32 + nt * 8 + q * 2;
            if (r0 < M) {
                *(float2*)&C[(size_t)r0 * N + c] = make_float2(acc[mt][nt][0], acc[mt][nt][1]);
                *(__half2*)&Ch[(size_t)r0 * N + c] = __floats2half2_rn(acc[mt][nt][0], acc[mt][nt][1]);
            }
            if (r0 + 8 < M) {
                *(float2*)&C[(size_t)(r0 + 8) * N + c] = make_float2(acc[mt][nt][2], acc[mt][nt][3]);
                *(__half2*)&Ch[(size_t)(r0 + 8) * N + c] = __floats2half2_rn(acc[mt][nt][2], acc[mt][nt][3]);
            }
        }
    }
}

// ---------------- attention dots ----------------
__global__ void k_attn1(const float* __restrict__ h1, const float* __restrict__ al,
                        const float* __restrict__ ar, float* __restrict__ el,
                        float* __restrict__ er) {
    int w = (blockIdx.x * blockDim.x + threadIdx.x) >> 5;
    if (w >= NN) return;
    int lane = threadIdx.x & 31;
    const float4* hp = (const float4*)(h1 + (size_t)w * F1);
    const float4* al4 = (const float4*)al;
    const float4* ar4 = (const float4*)ar;
    float4 h0 = hp[lane], h1v = hp[lane + 32];
    float4 a0 = al4[lane], a1 = al4[lane + 32];
    float4 r0 = ar4[lane], r1 = ar4[lane + 32];
    float elA = h0.x * a0.x + h0.y * a0.y + h0.z * a0.z + h0.w * a0.w;
    float elB = h1v.x * a1.x + h1v.y * a1.y + h1v.z * a1.z + h1v.w * a1.w;
    float erA = h0.x * r0.x + h0.y * r0.y + h0.z * r0.z + h0.w * r0.w;
    float erB = h1v.x * r1.x + h1v.y * r1.y + h1v.z * r1.z + h1v.w * r1.w;
    #pragma unroll
    for (int o = 4; o; o >>= 1) {
        elA += __shfl_xor_sync(FULL, elA, o);
        elB += __shfl_xor_sync(FULL, elB, o);
        erA += __shfl_xor_sync(FULL, erA, o);
        erB += __shfl_xor_sync(FULL, erB, o);
    }
    if ((lane & 7) == 0) {
        int h = lane >> 3;
        el[w * 8 + h]     = elA;
        el[w * 8 + 4 + h] = elB;
        er[w * 8 + h]     = erA;
        er[w * 8 + 4 + h] = erB;
    }
}

__global__ void k_attn2(const float* __restrict__ h2res, const float* __restrict__ al,
                        const float* __restrict__ ar, float* __restrict__ el,
                        float* __restrict__ er) {
    int w = (blockIdx.x * blockDim.x + threadIdx.x) >> 5;
    if (w >= NN) return;
    int lane = threadIdx.x & 31;
    const float2* hp = (const float2*)(h2res + (size_t)w * 128);
    float2 h = hp[lane];
    float2 av = ((const float2*)al)[lane];
    float2 rv = ((const float2*)ar)[lane];
    float a = h.x * av.x + h.y * av.y;
    float b = h.x * rv.x + h.y * rv.y;
    #pragma unroll
    for (int o = 16; o; o >>= 1) {
        a += __shfl_xor_sync(FULL, a, o);
        b += __shfl_xor_sync(FULL, b, o);
    }
    if (lane == 0) { el[w] = a; er[w] = b; }
}

// ---------------- layer-1 aggregation: fp16 gather, no shuffles ----------------
// lane covers features f = lane*8 .. lane*8+7, all in head (lane>>2).
__device__ __forceinline__ void hacc8(float* acc, uint4 v, float wgt) {
    const __half2* p = (const __half2*)&v;
    #pragma unroll
    for (int j = 0; j < 4; j++) {
        float2 f = __half22float2(p[j]);
        acc[2 * j]     += f.x * wgt;
        acc[2 * j + 1] += f.y * wgt;
    }
}

__global__ __launch_bounds__(256)
void k_agg1(const int* __restrict__ us, const int* __restrict__ off,
            const __half* __restrict__ h1h, const float* __restrict__ el,
            const float* __restrict__ er, const float* __restrict__ feats,
            const float* __restrict__ bias, float* __restrict__ x1) {
    int w = (blockIdx.x * blockDim.x + threadIdx.x) >> 5;
    if (w >= NN) return;
    int lane = threadIdx.x & 31;
    int h = lane >> 2;                       // head for this lane's 8 features
    int s0 = off[w], s1 = off[w + 1];
    float er_l = er[w * 8 + h];
    float s_l = 0.f;
    float acc[8] = {};

    int i = s0;
    for (; i + 4 <= s1; i += 4) {
        int u0 = us[i], u1 = us[i + 1], u2 = us[i + 2], u3 = us[i + 3];
        float e0 = el[u0 * 8 + h];
        float e1 = el[u1 * 8 + h];
        float e2 = el[u2 * 8 + h];
        float e3 = el[u3 * 8 + h];
        uint4 v0 = *(const uint4*)&h1h[(size_t)u0 * F1 + lane * 8];
        uint4 v1 = *(const uint4*)&h1h[(size_t)u1 * F1 + lane * 8];
        uint4 v2 = *(const uint4*)&h1h[(size_t)u2 * F1 + lane * 8];
        uint4 v3 = *(const uint4*)&h1h[(size_t)u3 * F1 + lane * 8];
        float t0 = e0 + er_l; t0 = t0 > 0.f ? t0 : NEG * t0;
        float t1 = e1 + er_l; t1 = t1 > 0.f ? t1 : NEG * t1;
        float t2 = e2 + er_l; t2 = t2 > 0.f ? t2 : NEG * t2;
        float t3 = e3 + er_l; t3 = t3 > 0.f ? t3 : NEG * t3;
        float w0 = __expf(t0), w1 = __expf(t1), w2 = __expf(t2), w3 = __expf(t3);
        s_l += (w0 + w1) + (w2 + w3);
        hacc8(acc, v0, w0);
        hacc8(acc, v1, w1);
        hacc8(acc, v2, w2);
        hacc8(acc, v3, w3);
    }
    for (; i < s1; i++) {
        int u = us[i];
        float e = el[u * 8 + h];
        uint4 v = *(const uint4*)&h1h[(size_t)u * F1 + lane * 8];
        float tt = e + er_l;
        tt = tt > 0.f ? tt : NEG * tt;
        float ww = __expf(tt);
        s_l += ww;
        hacc8(acc, v, ww);
    }

    float is = 1.f / s_l;
    int f = lane * 8;
    float4 f0 = *(const float4*)&feats[(size_t)w * FIN + f];
    float4 f1 = *(const float4*)&feats[(size_t)w * FIN + f + 4];
    float4 b0 = *(const float4*)&bias[f];
    float4 b1 = *(const float4*)&bias[f + 4];
    float o[8];
    o[0] = acc[0] * is + f0.x + b0.x;
    o[1] = acc[1] * is + f0.y + b0.y;
    o[2] = acc[2] * is + f0.z + b0.z;
    o[3] = acc[3] * is + f0.w + b0.w;
    o[4] = acc[4] * is + f1.x + b1.x;
    o[5] = acc[5] * is + f1.y + b1.y;
    o[6] = acc[6] * is + f1.z + b1.z;
    o[7] = acc[7] * is + f1.w + b1.w;
    #pragma unroll
    for (int j = 0; j < 8; j++)
        o[j] = o[j] > 0.f ? o[j] : expm1f(o[j]);
    *(float4*)&x1[(size_t)w * F1 + f]     = make_float4(o[0], o[1], o[2], o[3]);
    *(float4*)&x1[(size_t)w * F1 + f + 4] = make_float4(o[4], o[5], o[6], o[7]);
}

// ---------------- concat [W2 | res_W2] ----------------
__global__ void k_concat(const float* __restrict__ W2, const float* __restrict__ rw,
                         float* __restrict__ Bcat) {
    int i = blockIdx.x * blockDim.x + threadIdx.x;
    if (i < FIN * 128) {
        int k = i >> 7, c = i & 127;
        Bcat[i] = (c < 64) ? W2[k * 64 + c] : rw[k * 64 + (c - 64)];
    }
}

// ---------------- layer-2 aggregation: fp16 gather, no shuffles ----------------
__global__ __launch_bounds__(256)
void k_agg2(const int* __restrict__ us, const int* __restrict__ off,
            const __half* __restrict__ h2h, const float* __restrict__ h2res,
            const float* __restrict__ el, const float* __restrict__ er,
            const float* __restrict__ bias, float* __restrict__ out,
            int* __restrict__ deg) {
    int w = (blockIdx.x * blockDim.x + threadIdx.x) >> 5;
    if (w >= NN) return;
    int lane = threadIdx.x & 31;
    if (lane == 0) deg[w] = 0;    // reset histogram for next graph replay
    int s0 = off[w], s1 = off[w + 1];
    float erv = er[w];
    float s = 0.f;
    float2 acc = make_float2(0.f, 0.f);

    int i = s0;
    for (; i + 4 <= s1; i += 4) {
        int u0 = us[i], u1 = us[i + 1], u2 = us[i + 2], u3 = us[i + 3];
        float e0 = el[u0], e1 = el[u1], e2 = el[u2], e3 = el[u3];
        __half2 v0 = *(const __half2*)&h2h[(size_t)u0 * 128 + 2 * lane];
        __half2 v1 = *(const __half2*)&h2h[(size_t)u1 * 128 + 2 * lane];
        __half2 v2 = *(const __half2*)&h2h[(size_t)u2 * 128 + 2 * lane];
        __half2 v3 = *(const __half2*)&h2h[(size_t)u3 * 128 + 2 * lane];
        float t0 = e0 + erv; t0 = t0 > 0.f ? t0 : NEG * t0;
        float t1 = e1 + erv; t1 = t1 > 0.f ? t1 : NEG * t1;
        float t2 = e2 + erv; t2 = t2 > 0.f ? t2 : NEG * t2;
        float t3 = e3 + erv; t3 = t3 > 0.f ? t3 : NEG * t3;
        float w0 = __expf(t0), w1 = __expf(t1), w2 = __expf(t2), w3 = __expf(t3);
        s += (w0 + w1) + (w2 + w3);
        float2 f0 = __half22float2(v0), f1 = __half22float2(v1);
        float2 f2 = __half22float2(v2), f3 = __half22float2(v3);
        acc.x += f0.x * w0 + f1.x * w1 + f2.x * w2 + f3.x * w3;
        acc.y += f0.y * w0 + f1.y * w1 + f2.y * w2 + f3.y * w3;
    }
    for (; i < s1; i++) {
        int u = us[i];
        float tt = el[u] + erv;
        tt = tt > 0.f ? tt : NEG * tt;
        float e = __expf(tt);
        s += e;
        float2 f = __half22float2(*(const __half2*)&h2h[(size_t)u * 128 + 2 * lane]);
        acc.x += f.x * e;
        acc.y += f.y * e;
    }
    float is = 1.f / s;
    float2 rv = *(const float2*)&h2res[(size_t)w * 128 + 64 + 2 * lane];
    float2 bv = *(const float2*)&bias[2 * lane];
    float2 o;
    o.x = acc.x * is + rv.x + bv.x;
    o.y = acc.y * is + rv.y + bv.y;
    *(float2*)&out[(size_t)w * 64 + 2 * lane] = o;
}

// ---------------- launch ----------------
extern "C" void kernel_launch(void* const* d_in, const int* in_sizes, int n_in,
                              void* d_out, int out_size) {
    const float* feats = (const float*)d_in[0];
    const int*   src   = (const int*)d_in[1];
    const int*   dst   = (const int*)d_in[2];
    const float* W1    = (const float*)d_in[3];
    const float* al1   = (const float*)d_in[4];
    const float* ar1   = (const float*)d_in[5];
    const float* b1    = (const float*)d_in[6];
    const float* W2    = (const float*)d_in[7];
    const float* al2   = (const float*)d_in[8];
    const float* ar2   = (const float*)d_in[9];
    const float* b2    = (const float*)d_in[10];
    const float* rw2   = (const float*)d_in[11];
    float* out = (float*)d_out;
    int E = in_sizes[1];

    float *h1, *el1, *er1, *x1, *h2res, *el2, *er2, *Bcat;
    __half *h1h, *h2h;
    int *deg, *off, *us;
    cudaGetSymbolAddress((void**)&h1, g_h1);
    cudaGetSymbolAddress((void**)&h1h, g_h1h);
    cudaGetSymbolAddress((void**)&el1, g_el1);
    cudaGetSymbolAddress((void**)&er1, g_er1);
    cudaGetSymbolAddress((void**)&x1, g_x1);
    cudaGetSymbolAddress((void**)&h2res, g_h2res);
    cudaGetSymbolAddress((void**)&h2h, g_h2h);
    cudaGetSymbolAddress((void**)&el2, g_el2);
    cudaGetSymbolAddress((void**)&er2, g_er2);
    cudaGetSymbolAddress((void**)&Bcat, g_Bcat);
    cudaGetSymbolAddress((void**)&deg, g_deg);
    cudaGetSymbolAddress((void**)&off, g_off);
    cudaGetSymbolAddress((void**)&us, g_us);

    static cudaStream_t side = nullptr;
    static cudaEvent_t evFork = nullptr, evJoin1 = nullptr;
    if (!side) {
        cudaStreamCreateWithFlags(&side, cudaStreamNonBlocking);
        cudaEventCreateWithFlags(&evFork, cudaEventDisableTiming);
        cudaEventCreateWithFlags(&evJoin1, cudaEventDisableTiming);
    }

    int eb = (E + 255) / 256;
    int wb = (NN * 32 + 255) / 256;

    // fork: CSR build + concat on side stream (deg arrives zeroed: static init on
    // call 1, re-zeroed by k_agg2 on every run/replay)
    cudaEventRecord(evFork, 0);
    cudaStreamWaitEvent(side, evFork, 0);
    k_hist<<<eb, 256, 0, side>>>(dst, E, deg);
    k_scan<<<1, 1024, 0, side>>>(deg, off, NN);
    k_scatter<<<eb, 256, 0, side>>>(src, dst, E, off, deg, us);
    k_concat<<<(FIN * 128 + 255) / 256, 256, 0, side>>>(W2, rw2, Bcat);
    cudaEventRecord(evJoin1, side);

    // main: layer-1 dense part (overlaps CSR build)
    k_mma_gemm<<<dim3((NN + 127) / 128, F1 / 64), 256>>>(feats, W1, h1, h1h, NN, F1, FIN);
    k_attn1<<<wb, 256>>>(h1, al1, ar1, el1, er1);

    cudaStreamWaitEvent(0, evJoin1, 0);
    k_agg1<<<wb, 256>>>(us, off, h1h, el1, er1, feats, b1, x1);

    // layer 2
    k_mma_gemm<<<dim3((NN + 127) / 128, 128 / 64), 256>>>(x1, Bcat, h2res, h2h, NN, 128, FIN);
    k_attn2<<<wb, 256>>>(h2res, al2, ar2, el2, er2);
    k_agg2<<<wb, 256>>>(us, off, h2h, h2res, el2, er2, b2, out, deg);
}

// round 10
// speedup vs baseline: 1.0149x; 1.0149x over previous
#include <cuda_runtime.h>
#include <math.h>

#define NN   50000
#define FIN  256
#define H1N  8
#define F1   256
#define NEG  0.2f
#define EMAX 900000
#define FULL 0xffffffffu

// ---------------- scratch ----------------
__device__ __align__(256) float g_h1[NN * F1];
__device__ __align__(256) float g_el1[NN * H1N];
__device__ __align__(256) float g_er1[NN * H1N];
__device__ __align__(256) float g_x1[NN * F1];
__device__ __align__(256) float g_h2res[NN * 128];   // [h2 (64) | residual (64)]
__device__ __align__(256) float g_el2[NN];           // zero at load; agg1 re-zeroes each run
__device__ __align__(256) float g_er2[NN];
__device__ int g_deg[NN];          // zeroed at load; re-zeroed by k_agg2 each run
__device__ int g_off[NN + 1];
__device__ int g_us[EMAX];

// ---------------- CSR build ----------------
__global__ void k_hist(const int* __restrict__ dst, int E, int* __restrict__ deg) {
    int i = blockIdx.x * blockDim.x + threadIdx.x;
    if (i < E) atomicAdd(&deg[dst[i]], 1);
}

// single-block scan; also zeroes deg so k_scatter can reuse it as its cursor
__global__ void k_scan(int* __restrict__ deg, int* __restrict__ off, int n) {
    __shared__ int wsum[32];
    __shared__ int carry;
    int tid = threadIdx.x, lane = tid & 31, wid = tid >> 5;
    if (tid == 0) carry = 0;
    __syncthreads();
    for (int base = 0; base < n; base += 1024) {
        int i = base + tid;
        int v = 0;
        if (i < n) { v = deg[i]; deg[i] = 0; }
        int x = v;
        #pragma unroll
        for (int o = 1; o < 32; o <<= 1) {
            int y = __shfl_up_sync(FULL, x, o);
            if (lane >= o) x += y;
        }
        if (lane == 31) wsum[wid] = x;
        __syncthreads();
        if (wid == 0) {
            int w = wsum[lane];
            #pragma unroll
            for (int o = 1; o < 32; o <<= 1) {
                int y = __shfl_up_sync(FULL, w, o);
                if (lane >= o) w += y;
            }
            wsum[lane] = w;
        }
        __syncthreads();
        int incl = x + (wid ? wsum[wid - 1] : 0) + carry;
        if (i < n) off[i] = incl - v;
        __syncthreads();
        if (tid == 1023) carry = incl;
        __syncthreads();
    }
    if (tid == 0) off[n] = carry;
}

__global__ void k_scatter(const int* __restrict__ src, const int* __restrict__ dst,
                          int E, const int* __restrict__ off, int* __restrict__ cur,
                          int* __restrict__ us) {
    int i = blockIdx.x * blockDim.x + threadIdx.x;
    if (i < E) {
        int d = dst[i];
        int p = off[d] + atomicAdd(&cur[d], 1);
        us[p] = src[i];
    }
}

// ---------------- TF32 tensor-core GEMM with fused attention-dot epilogue --------
// mode 0: plain.  mode 1 (layer1): per-block 2 heads, head = 2*blockIdx.y + warpN,
//         el/er written directly (each (row,head) owned by one quad).
// mode 2 (layer2): blockIdx.y==0 covers the single 64-wide head; quad partials
//         atomicAdd'ed into el/er (zeroed by k_agg1 earlier in the same run).
// B2 != null: split-B mode (GEMM2): blockIdx.y==0 -> B (W2), ==1 -> B2 (res_W2),
//         both 64 columns wide.
__device__ __forceinline__ unsigned f2tf(float x) {
    unsigned u;
    asm("cvt.rna.tf32.f32 %0, %1;" : "=r"(u) : "f"(x));
    return u;
}

__device__ __forceinline__ void mma_tf32(float* d, const unsigned* a, const unsigned* b) {
    asm volatile(
        "mma.sync.aligned.m16n8k8.row.col.f32.tf32.tf32.f32 "
        "{%0,%1,%2,%3}, {%4,%5,%6,%7}, {%8,%9}, {%0,%1,%2,%3};\n"
        : "+f"(d[0]), "+f"(d[1]), "+f"(d[2]), "+f"(d[3])
        : "r"(a[0]), "r"(a[1]), "r"(a[2]), "r"(a[3]), "r"(b[0]), "r"(b[1]));
}

__global__ __launch_bounds__(256)
void k_mma_gemm(const float* __restrict__ A, const float* __restrict__ B,
                const float* __restrict__ B2, float* __restrict__ C,
                int M, int N, int K,
                const float* __restrict__ al, const float* __restrict__ ar,
                float* __restrict__ el, float* __restrict__ er, int mode) {
    __shared__ unsigned As[128][36];
    __shared__ unsigned Bs[32][72];
    int t = threadIdx.x;
    int lane = t & 31;
    int warp = t >> 5;
    int g = lane >> 2, q = lane & 3;
    int warpM = warp & 3, warpN = warp >> 2;
    int bm = blockIdx.x * 128, bn = blockIdx.y * 64;

    const float* Bp = B;
    int ldB = N, bcol = bn;
    if (B2) {                       // split-B: two independent 64-wide matrices
        Bp = (blockIdx.y == 0) ? B : B2;
        ldB = 64; bcol = 0;
    }

    float4 avs[4], bvs[2];
    float acc[2][4][4] = {};

    auto loadA = [&](int kt) {
        #pragma unroll
        for (int i = 0; i < 4; i++) {
            int idx = t + i * 256;
            int r = idx >> 3, c4 = (idx & 7) * 4;
            float4 v = make_float4(0.f, 0.f, 0.f, 0.f);
            if (bm + r < M)
                v = *(const float4*)&A[(size_t)(bm + r) * K + kt + c4];
            avs[i] = v;
        }
    };
    auto loadB = [&](int kt) {
        #pragma unroll
        for (int i = 0; i < 2; i++) {
            int idx = t + i * 256;
            int r = idx >> 4, c4 = (idx & 15) * 4;
            bvs[i] = *(const float4*)&Bp[(size_t)(kt + r) * ldB + bcol + c4];
        }
    };
    auto stage = [&]() {
        #pragma unroll
        for (int i = 0; i < 4; i++) {
            int idx = t + i * 256;
            int r = idx >> 3, c4 = (idx & 7) * 4;
            As[r][c4 + 0] = f2tf(avs[i].x);
            As[r][c4 + 1] = f2tf(avs[i].y);
            As[r][c4 + 2] = f2tf(avs[i].z);
            As[r][c4 + 3] = f2tf(avs[i].w);
        }
        #pragma unroll
        for (int i = 0; i < 2; i++) {
            int idx = t + i * 256;
            int r = idx >> 4, c4 = (idx & 15) * 4;
            Bs[r][c4 + 0] = f2tf(bvs[i].x);
            Bs[r][c4 + 1] = f2tf(bvs[i].y);
            Bs[r][c4 + 2] = f2tf(bvs[i].z);
            Bs[r][c4 + 3] = f2tf(bvs[i].w);
        }
    };

    loadA(0); loadB(0);
    stage();
    __syncthreads();

    for (int kt = 0; kt < K; kt += 32) {
        bool nxt = (kt + 32) < K;
        if (nxt) { loadA(kt + 32); loadB(kt + 32); }

        #pragma unroll
        for (int ks = 0; ks < 4; ks++) {
            int k0 = ks * 8;
            unsigned af[2][4], bf[4][2];
            #pragma unroll
            for (int mt = 0; mt < 2; mt++) {
                int rb = warpM * 32 + mt * 16;
                af[mt][0] = As[rb + g][k0 + q];
                af[mt][1] = As[rb + g + 8][k0 + q];
                af[mt][2] = As[rb + g][k0 + q + 4];
                af[mt][3] = As[rb + g + 8][k0 + q + 4];
            }
            #pragma unroll
            for (int nt = 0; nt < 4; nt++) {
                int cb = warpN * 32 + nt * 8;
                bf[nt][0] = Bs[k0 + q][cb + g];
                bf[nt][1] = Bs[k0 + q + 4][cb + g];
            }
            #pragma unroll
            for (int mt = 0; mt < 2; mt++)
                #pragma unroll
                for (int nt = 0; nt < 4; nt++)
                    mma_tf32(acc[mt][nt], af[mt], bf[nt]);
        }
        if (nxt) {
            __syncthreads();
            stage();
            __syncthreads();
        }
    }

    // ---- C store ----
    #pragma unroll
    for (int mt = 0; mt < 2; mt++) {
        int r0 = bm + warpM * 32 + mt * 16 + g;
        #pragma unroll
        for (int nt = 0; nt < 4; nt++) {
            int c = bn + warpN * 32 + nt * 8 + q * 2;
            if (r0 < M)
                *(float2*)&C[(size_t)r0 * N + c] = make_float2(acc[mt][nt][0], acc[mt][nt][1]);
            if (r0 + 8 < M)
                *(float2*)&C[(size_t)(r0 + 8) * N + c] = make_float2(acc[mt][nt][2], acc[mt][nt][3]);
        }
    }

    // ---- fused attention-dot epilogue ----
    if (mode == 1 || (mode == 2 && blockIdx.y == 0)) {
        // thread's 8 columns all belong to one head
        float alv[8], arv[8];
        #pragma unroll
        for (int nt = 0; nt < 4; nt++) {
            int cl;
            if (mode == 1) {
                int head = 2 * blockIdx.y + warpN;
                cl = head * 32 + nt * 8 + q * 2;     // al is [H1][32]
            } else {
                cl = warpN * 32 + nt * 8 + q * 2;     // al is [1][64]
            }
            alv[2 * nt]     = al[cl];
            alv[2 * nt + 1] = al[cl + 1];
            arv[2 * nt]     = ar[cl];
            arv[2 * nt + 1] = ar[cl + 1];
        }
        #pragma unroll
        for (int mt = 0; mt < 2; mt++) {
            float pel0 = 0.f, pel1 = 0.f, per0 = 0.f, per1 = 0.f;
            #pragma unroll
            for (int nt = 0; nt < 4; nt++) {
                pel0 += acc[mt][nt][0] * alv[2 * nt] + acc[mt][nt][1] * alv[2 * nt + 1];
                pel1 += acc[mt][nt][2] * alv[2 * nt] + acc[mt][nt][3] * alv[2 * nt + 1];
                per0 += acc[mt][nt][0] * arv[2 * nt] + acc[mt][nt][1] * arv[2 * nt + 1];
                per1 += acc[mt][nt][2] * arv[2 * nt] + acc[mt][nt][3] * arv[2 * nt + 1];
            }
            #pragma unroll
            for (int o = 1; o <= 2; o <<= 1) {       // reduce over q (quad)
                pel0 += __shfl_xor_sync(FULL, pel0, o);
                pel1 += __shfl_xor_sync(FULL, pel1, o);
                per0 += __shfl_xor_sync(FULL, per0, o);
                per1 += __shfl_xor_sync(FULL, per1, o);
            }
            if (q == 0) {
                int r = bm + warpM * 32 + mt * 16 + g;
                if (mode == 1) {
                    int head = 2 * blockIdx.y + warpN;
                    if (r < M)     { el[r * 8 + head] = pel0; er[r * 8 + head] = per0; }
                    if (r + 8 < M) { el[(r + 8) * 8 + head] = pel1; er[(r + 8) * 8 + head] = per1; }
                } else {
                    // two warpN halves contribute; el/er pre-zeroed by k_agg1
                    if (r < M)     { atomicAdd(&el[r], pel0); atomicAdd(&er[r], per0); }
                    if (r + 8 < M) { atomicAdd(&el[r + 8], pel1); atomicAdd(&er[r + 8], per1); }
                }
            }
        }
    }
}

// ---------------- layer-1 aggregation: single-pass, 4-edge unrolled (fp32) -------
// Also zeroes el2/er2 for this run's GEMM2 atomic epilogue.
__global__ __launch_bounds__(256)
void k_agg1(const int* __restrict__ us, const int* __restrict__ off,
            const float* __restrict__ h1, const float* __restrict__ el,
            const float* __restrict__ er, const float* __restrict__ feats,
            const float* __restrict__ bias, float* __restrict__ x1,
            float* __restrict__ el2, float* __restrict__ er2) {
    int w = (blockIdx.x * blockDim.x + threadIdx.x) >> 5;
    if (w >= NN) return;
    int lane = threadIdx.x & 31;
    if (lane == 0) { el2[w] = 0.f; er2[w] = 0.f; }
    int s0 = off[w], s1 = off[w + 1];
    int hA = lane >> 3, hB = 4 + (lane >> 3);

    float er_l = (lane < 8) ? er[w * 8 + lane] : 0.f;
    float s_l = 0.f;
    float4 acc0 = make_float4(0.f, 0.f, 0.f, 0.f);
    float4 acc1 = make_float4(0.f, 0.f, 0.f, 0.f);

    int i = s0;
    for (; i + 4 <= s1; i += 4) {
        int u0 = us[i], u1 = us[i + 1], u2 = us[i + 2], u3 = us[i + 3];
        float e0 = 0.f, e1 = 0.f, e2 = 0.f, e3 = 0.f;
        if (lane < 8) {
            e0 = el[u0 * 8 + lane];
            e1 = el[u1 * 8 + lane];
            e2 = el[u2 * 8 + lane];
            e3 = el[u3 * 8 + lane];
        }
        const float4* p0 = (const float4*)(h1 + (size_t)u0 * F1);
        const float4* p1 = (const float4*)(h1 + (size_t)u1 * F1);
        const float4* p2 = (const float4*)(h1 + (size_t)u2 * F1);
        const float4* p3 = (const float4*)(h1 + (size_t)u3 * F1);
        float4 x0 = p0[lane], y0 = p0[lane + 32];
        float4 x1v = p1[lane], y1 = p1[lane + 32];
        float4 x2 = p2[lane], y2 = p2[lane + 32];
        float4 x3 = p3[lane], y3 = p3[lane + 32];

        float t0 = e0 + er_l; t0 = t0 > 0.f ? t0 : NEG * t0;
        float t1 = e1 + er_l; t1 = t1 > 0.f ? t1 : NEG * t1;
        float t2 = e2 + er_l; t2 = t2 > 0.f ? t2 : NEG * t2;
        float t3 = e3 + er_l; t3 = t3 > 0.f ? t3 : NEG * t3;
        float w0 = __expf(t0), w1 = __expf(t1), w2 = __expf(t2), w3 = __expf(t3);
        s_l += (w0 + w1) + (w2 + w3);

        float a0A = __shfl_sync(FULL, w0, hA), a0B = __shfl_sync(FULL, w0, hB);
        float a1A = __shfl_sync(FULL, w1, hA), a1B = __shfl_sync(FULL, w1, hB);
        float a2A = __shfl_sync(FULL, w2, hA), a2B = __shfl_sync(FULL, w2, hB);
        float a3A = __shfl_sync(FULL, w3, hA), a3B = __shfl_sync(FULL, w3, hB);

        acc0.x += x0.x * a0A + x1v.x * a1A + x2.x * a2A + x3.x * a3A;
        acc0.y += x0.y * a0A + x1v.y * a1A + x2.y * a2A + x3.y * a3A;
        acc0.z += x0.z * a0A + x1v.z * a1A + x2.z * a2A + x3.z * a3A;
        acc0.w += x0.w * a0A + x1v.w * a1A + x2.w * a2A + x3.w * a3A;
        acc1.x += y0.x * a0B + y1.x * a1B + y2.x * a2B + y3.x * a3B;
        acc1.y += y0.y * a0B + y1.y * a1B + y2.y * a2B + y3.y * a3B;
        acc1.z += y0.z * a0B + y1.z * a1B + y2.z * a2B + y3.z * a3B;
        acc1.w += y0.w * a0B + y1.w * a1B + y2.w * a2B + y3.w * a3B;
    }
    for (; i < s1; i++) {
        int u = us[i];
        float e = (lane < 8) ? el[u * 8 + lane] : 0.f;
        const float4* hu = (const float4*)(h1 + (size_t)u * F1);
        float4 b0 = hu[lane], b1 = hu[lane + 32];
        float tt = e + er_l;
        tt = tt > 0.f ? tt : NEG * tt;
        float ewl = __expf(tt);
        s_l += ewl;
        float aA = __shfl_sync(FULL, ewl, hA);
        float aB = __shfl_sync(FULL, ewl, hB);
        acc0.x += b0.x * aA; acc0.y += b0.y * aA; acc0.z += b0.z * aA; acc0.w += b0.w * aA;
        acc1.x += b1.x * aB; acc1.y += b1.y * aB; acc1.z += b1.z * aB; acc1.w += b1.w * aB;
    }

    float is_l = (lane < 8) ? 1.f / s_l : 0.f;
    float isA = __shfl_sync(FULL, is_l, hA);
    float isB = __shfl_sync(FULL, is_l, hB);

    const float4* fp = (const float4*)(feats + (size_t)w * FIN);
    const float4* bp = (const float4*)bias;
    float4 f0 = fp[lane], f1 = fp[lane + 32];
    float4 bA = bp[lane], bB = bp[lane + 32];
    float4 o0, o1;
    o0.x = acc0.x * isA + f0.x + bA.x;  o0.y = acc0.y * isA + f0.y + bA.y;
    o0.z = acc0.z * isA + f0.z + bA.z;  o0.w = acc0.w * isA + f0.w + bA.w;
    o1.x = acc1.x * isB + f1.x + bB.x;  o1.y = acc1.y * isB + f1.y + bB.y;
    o1.z = acc1.z * isB + f1.z + bB.z;  o1.w = acc1.w * isB + f1.w + bB.w;
    o0.x = o0.x > 0.f ? o0.x : expm1f(o0.x);
    o0.y = o0.y > 0.f ? o0.y : expm1f(o0.y);
    o0.z = o0.z > 0.f ? o0.z : expm1f(o0.z);
    o0.w = o0.w > 0.f ? o0.w : expm1f(o0.w);
    o1.x = o1.x > 0.f ? o1.x : expm1f(o1.x);
    o1.y = o1.y > 0.f ? o1.y : expm1f(o1.y);
    o1.z = o1.z > 0.f ? o1.z : expm1f(o1.z);
    o1.w = o1.w > 0.f ? o1.w : expm1f(o1.w);
    float4* xp = (float4*)(x1 + (size_t)w * F1);
    xp[lane] = o0;
    xp[lane + 32] = o1;
}

// ---------------- layer-2 aggregation (re-zeroes deg for next replay) -----------
__global__ __launch_bounds__(256)
void k_agg2(const int* __restrict__ us, const int* __restrict__ off,
            const float* __restrict__ h2res, const float* __restrict__ el,
            const float* __restrict__ er, const float* __restrict__ bias,
            float* __restrict__ out, int* __restrict__ deg) {
    int w = (blockIdx.x * blockDim.x + threadIdx.x) >> 5;
    if (w >= NN) return;
    int lane = threadIdx.x & 31;
    if (lane == 0) deg[w] = 0;    // reset histogram for next graph replay
    int s0 = off[w], s1 = off[w + 1];
    float erv = er[w];
    float s = 0.f;
    float2 acc = make_float2(0.f, 0.f);

    int i = s0;
    for (; i + 4 <= s1; i += 4) {
        int u0 = us[i], u1 = us[i + 1], u2 = us[i + 2], u3 = us[i + 3];
        float e0 = el[u0], e1 = el[u1], e2 = el[u2], e3 = el[u3];
        float2 b0 = *(const float2*)&h2res[(size_t)u0 * 128 + 2 * lane];
        float2 b1 = *(const float2*)&h2res[(size_t)u1 * 128 + 2 * lane];
        float2 b2 = *(const float2*)&h2res[(size_t)u2 * 128 + 2 * lane];
        float2 b3 = *(const float2*)&h2res[(size_t)u3 * 128 + 2 * lane];
        float t0 = e0 + erv; t0 = t0 > 0.f ? t0 : NEG * t0;
        float t1 = e1 + erv; t1 = t1 > 0.f ? t1 : NEG * t1;
        float t2 = e2 + erv; t2 = t2 > 0.f ? t2 : NEG * t2;
        float t3 = e3 + erv; t3 = t3 > 0.f ? t3 : NEG * t3;
        float w0 = __expf(t0), w1 = __expf(t1), w2 = __expf(t2), w3 = __expf(t3);
        s += (w0 + w1) + (w2 + w3);
        acc.x += b0.x * w0 + b1.x * w1 + b2.x * w2 + b3.x * w3;
        acc.y += b0.y * w0 + b1.y * w1 + b2.y * w2 + b3.y * w3;
    }
    for (; i < s1; i++) {
        int u = us[i];
        float tt = el[u] + erv;
        tt = tt > 0.f ? tt : NEG * tt;
        float e = __expf(tt);
        s += e;
        float2 b = *(const float2*)&h2res[(size_t)u * 128 + 2 * lane];
        acc.x += b.x * e;
        acc.y += b.y * e;
    }
    float is = 1.f / s;
    float2 rv = *(const float2*)&h2res[(size_t)w * 128 + 64 + 2 * lane];
    float2 bv = *(const float2*)&bias[2 * lane];
    float2 o;
    o.x = acc.x * is + rv.x + bv.x;
    o.y = acc.y * is + rv.y + bv.y;
    *(float2*)&out[(size_t)w * 64 + 2 * lane] = o;
}

// ---------------- launch ----------------
extern "C" void kernel_launch(void* const* d_in, const int* in_sizes, int n_in,
                              void* d_out, int out_size) {
    const float* feats = (const float*)d_in[0];
    const int*   src   = (const int*)d_in[1];
    const int*   dst   = (const int*)d_in[2];
    const float* W1    = (const float*)d_in[3];
    const float* al1   = (const float*)d_in[4];
    const float* ar1   = (const float*)d_in[5];
    const float* b1    = (const float*)d_in[6];
    const float* W2    = (const float*)d_in[7];
    const float* al2   = (const float*)d_in[8];
    const float* ar2   = (const float*)d_in[9];
    const float* b2    = (const float*)d_in[10];
    const float* rw2   = (const float*)d_in[11];
    float* out = (float*)d_out;
    int E = in_sizes[1];

    float *h1, *el1, *er1, *x1, *h2res, *el2, *er2;
    int *deg, *off, *us;
    cudaGetSymbolAddress((void**)&h1, g_h1);
    cudaGetSymbolAddress((void**)&el1, g_el1);
    cudaGetSymbolAddress((void**)&er1, g_er1);
    cudaGetSymbolAddress((void**)&x1, g_x1);
    cudaGetSymbolAddress((void**)&h2res, g_h2res);
    cudaGetSymbolAddress((void**)&el2, g_el2);
    cudaGetSymbolAddress((void**)&er2, g_er2);
    cudaGetSymbolAddress((void**)&deg, g_deg);
    cudaGetSymbolAddress((void**)&off, g_off);
    cudaGetSymbolAddress((void**)&us, g_us);

    static cudaStream_t side = nullptr;
    static cudaEvent_t evFork = nullptr, evJoin1 = nullptr;
    if (!side) {
        cudaStreamCreateWithFlags(&side, cudaStreamNonBlocking);
        cudaEventCreateWithFlags(&evFork, cudaEventDisableTiming);
        cudaEventCreateWithFlags(&evJoin1, cudaEventDisableTiming);
    }

    int eb = (E + 255) / 256;
    int wb = (NN * 32 + 255) / 256;

    // fork: CSR build on side stream (deg zeroed: static init on call 1, then by
    // k_agg2 every run/replay; el2/er2 zeroed by k_agg1 before GEMM2 accumulates)
    cudaEventRecord(evFork, 0);
    cudaStreamWaitEvent(side, evFork, 0);
    k_hist<<<eb, 256, 0, side>>>(dst, E, deg);                  // 1
    k_scan<<<1, 1024, 0, side>>>(deg, off, NN);                 // 2 (zeroes deg)
    k_scatter<<<eb, 256, 0, side>>>(src, dst, E, off, deg, us); // 3
    cudaEventRecord(evJoin1, side);

    // layer 1: GEMM + fused attn1 epilogue (overlaps CSR build)
    k_mma_gemm<<<dim3((NN + 127) / 128, F1 / 64), 256>>>(
        feats, W1, nullptr, h1, NN, F1, FIN, al1, ar1, el1, er1, 1);  // 4

    cudaStreamWaitEvent(0, evJoin1, 0);
    k_agg1<<<wb, 256>>>(us, off, h1, el1, er1, feats, b1, x1, el2, er2);  // 5

    // layer 2: split-B GEMM (W2 | res_W2) + fused attn2 atomic epilogue
    k_mma_gemm<<<dim3((NN + 127) / 128, 2), 256>>>(
        x1, W2, rw2, h2res, NN, 128, FIN, al2, ar2, el2, er2, 2);     // 6

    k_agg2<<<wb, 256>>>(us, off, h2res, el2, er2, b2, out, deg);      // 7
}